// round 5
// baseline (speedup 1.0000x reference)
#include <cuda_runtime.h>
#include <cuda_bf16.h>
#include <cstdint>

#define IMGS   128
#define EMB    256
#define NPIX   32768
#define VOCAB  4096

__device__ float g_csq[VOCAB];          // ||c||^2 exact fp32
__device__ float g_csqh[VOCAB];         // csq * 0.5f
__device__ float g_zsq[NPIX];
__device__ int   g_tok[NPIX];
__device__ __nv_bfloat16 g_cbh[VOCAB * EMB];
__device__ unsigned short g_cand[NPIX][16];
__device__ int   g_cnt[NPIX];

__device__ __forceinline__ unsigned int f2ord(float f) {
    unsigned int u = __float_as_uint(f);
    return (u & 0x80000000u) ? ~u : (u | 0x80000000u);
}
__device__ __forceinline__ uint32_t smem_u32(const void* p) {
    uint32_t a;
    asm("{ .reg .u64 t; cvta.to.shared.u64 t, %1; cvt.u32.u64 %0, t; }" : "=r"(a) : "l"(p));
    return a;
}

#define LDM4(r0, r1, r2, r3, addr)                                              \
    asm volatile("ldmatrix.sync.aligned.m8n8.x4.shared.b16 {%0,%1,%2,%3}, [%4];"\
        : "=r"(r0), "=r"(r1), "=r"(r2), "=r"(r3) : "r"(addr))

#define MMA16816(d, a0, a1, a2, a3, b0, b1)                                     \
    asm volatile("mma.sync.aligned.m16n8k16.row.col.f32.bf16.bf16.f32 "         \
        "{%0,%1,%2,%3},{%4,%5,%6,%7},{%8,%9},{%0,%1,%2,%3};"                    \
        : "+f"((d)[0]), "+f"((d)[1]), "+f"((d)[2]), "+f"((d)[3])                \
        : "r"(a0), "r"(a1), "r"(a2), "r"(a3), "r"(b0), "r"(b1))

#define CPA16(dst, src)                                                         \
    asm volatile("cp.async.cg.shared.global [%0], [%1], 16;" :: "r"(dst), "l"(src))
#define CP_COMMIT() asm volatile("cp.async.commit_group;" ::: "memory")

// ---------------------------------------------------------------------------
__global__ void k_init(const float* __restrict__ cb) {
    int t = threadIdx.x;
    int r = blockIdx.x * 4 + (t >> 5);
    int lane = t & 31;
    if (r < VOCAB) {
        const float* row = cb + r * EMB;
        float s = 0.f;
        #pragma unroll 4
        for (int e = lane; e < EMB; e += 32) { float v = row[e]; s += v * v; }
        #pragma unroll
        for (int o = 16; o; o >>= 1) s += __shfl_down_sync(0xFFFFFFFFu, s, o);
        if (lane == 0) { g_csq[r] = s; g_csqh[r] = 0.5f * s; }
    }
}
__global__ void k_cbh(const float* __restrict__ cb) {
    int i = blockIdx.x * 256 + threadIdx.x;
    g_cbh[i] = __float2bfloat16(cb[i]);
}

// ---------------------------------------------------------------------------
// fp32 256x256x256 GEMM (pre/post)
// ---------------------------------------------------------------------------
template<bool XFORM>
__global__ void __launch_bounds__(256) k_gemm256(
    const float* __restrict__ W, const float* __restrict__ bias,
    const float* __restrict__ In, float* __restrict__ Out)
{
    __shared__ float Ws[16][68];
    __shared__ float Bs[16][64];
    const int img = blockIdx.z;
    const int m0 = blockIdx.y * 64, n0 = blockIdx.x * 64;
    const float* in = In + (size_t)img * 65536;
    float* out = Out + (size_t)img * 65536;
    const int t = threadIdx.x;
    const int ty = t >> 4, tx = t & 15;
    float acc[4][4] = {};
    for (int k0 = 0; k0 < 256; k0 += 16) {
        {
            int row = t >> 2, c4 = (t & 3) * 4;
            float4 w4 = *reinterpret_cast<const float4*>(&W[(m0 + row) * 256 + k0 + c4]);
            Ws[c4 + 0][row] = w4.x; Ws[c4 + 1][row] = w4.y;
            Ws[c4 + 2][row] = w4.z; Ws[c4 + 3][row] = w4.w;
        }
        {
            int kk = t >> 4, n4 = (t & 15) * 4;
            float4 b4 = *reinterpret_cast<const float4*>(&in[(k0 + kk) * 256 + n0 + n4]);
            if (XFORM) {
                b4.x = 2.f * b4.x - 1.f; b4.y = 2.f * b4.y - 1.f;
                b4.z = 2.f * b4.z - 1.f; b4.w = 2.f * b4.w - 1.f;
            }
            *reinterpret_cast<float4*>(&Bs[kk][n4]) = b4;
        }
        __syncthreads();
        #pragma unroll
        for (int kk = 0; kk < 16; kk++) {
            float a[4], b[4];
            *reinterpret_cast<float4*>(a) = *reinterpret_cast<float4*>(&Ws[kk][ty * 4]);
            *reinterpret_cast<float4*>(b) = *reinterpret_cast<float4*>(&Bs[kk][tx * 4]);
            #pragma unroll
            for (int i = 0; i < 4; i++)
                #pragma unroll
                for (int j = 0; j < 4; j++)
                    acc[i][j] += a[i] * b[j];
        }
        __syncthreads();
    }
    #pragma unroll
    for (int i = 0; i < 4; i++) {
        int m = m0 + ty * 4 + i;
        float bm = bias[m];
        float4 o;
        o.x = acc[i][0] + bm; o.y = acc[i][1] + bm;
        o.z = acc[i][2] + bm; o.w = acc[i][3] + bm;
        *reinterpret_cast<float4*>(&out[m * 256 + n0 + tx * 4]) = o;
    }
}

__global__ void k_zsq(const float* __restrict__ z) {
    int img = blockIdx.x, hw = threadIdx.x;
    const float* p = z + (size_t)img * 65536 + hw;
    float s = 0.f;
    #pragma unroll 8
    for (int e = 0; e < 256; e++) { float v = p[e * 256]; s += v * v; }
    g_zsq[img * 256 + hw] = s;
}

// ---------------------------------------------------------------------------
// bf16 mma.sync distance-score GEMM + per-pixel serial prune (v2: low regs).
// CTA: 128 pixels x 4096 codes. Tile = 64 codes x 128 emb (kc = 2 chunks).
// Warp w: pixels w*16..+15 x 64 codes; acc[8][4] = 32 regs.
// Candidate ring (16) lives in SMEM. Score s = dot_bf16 - csq/2.
// SMEM: A 64KB | B0 16KB | B1 16KB | stg 8x1088 | csq 256B | ring 4KB
// ---------------------------------------------------------------------------
#define AOFF      0
#define B0OFF     65536
#define B1OFF     81920
#define STGOFF    98304
#define CSQOFF    107008
#define RINGOFF   107264
#define SMEM_DIST 111616
#define MARGIN    2.5e-5f

__global__ void __launch_bounds__(256, 2) k_dist_mma(const float* __restrict__ z) {
    extern __shared__ char smem[];
    const uint32_t sb = smem_u32(smem);
    const int t = threadIdx.x;
    const int wid = t >> 5, lane = t & 31;
    const int n_base = blockIdx.x * 128;

    // ---- A build: z (fp32 [e][pix]) -> bf16 swizzled [pix][e] (scratch = B0) ----
    {
        const float* zsrc = z + (size_t)(n_base >> 8) * 65536 + (n_base & 255);
        float* scr = reinterpret_cast<float*>(smem + B0OFF);   // 32e x 128pix fp32
        for (int kb = 0; kb < 8; kb++) {
            int e_l = t >> 3;
            int pg = (t & 7) * 16;
            const float4* s4 = reinterpret_cast<const float4*>(zsrc + (kb * 32 + e_l) * 256 + pg);
            float4 v0 = s4[0], v1 = s4[1], v2 = s4[2], v3 = s4[3];
            float4* d4 = reinterpret_cast<float4*>(scr + e_l * 128 + pg);
            d4[0] = v0; d4[1] = v1; d4[2] = v2; d4[3] = v3;
            __syncthreads();
            int pix = t & 127, half = t >> 7;
            #pragma unroll
            for (int jj = 0; jj < 8; jj++) {
                int el0 = (half * 8 + jj) * 2;
                float a = scr[el0 * 128 + pix], b = scr[(el0 + 1) * 128 + pix];
                uint32_t u;
                asm("cvt.rn.bf16x2.f32 %0, %1, %2;" : "=r"(u) : "f"(b), "f"(a));
                int eg = kb * 32 + el0;
                uint32_t unit = (uint32_t)(eg >> 3) ^ (uint32_t)(pix & 7);
                uint32_t addr = sb + AOFF + (uint32_t)pix * 512 + unit * 16 + (eg & 7) * 2;
                asm volatile("st.shared.b32 [%0], %1;" :: "r"(addr), "r"(u) : "memory");
            }
            __syncthreads();
        }
    }

    const int wbase = wid * 16;
    const int arow = wbase + (lane & 7) + ((lane >> 3) & 1) * 8;
    const uint32_t aswz = (uint32_t)(arow & 7);
    const uint32_t abase = sb + AOFF + (uint32_t)arow * 512;
    const int ag2 = lane >> 4;
    const int brp = ((lane >> 4) & 1) * 8 + (lane & 7);
    const int bg1 = (lane >> 3) & 1;
    float* stg = reinterpret_cast<float*>(smem + STGOFF + wid * 1088);
    float* csq_s = reinterpret_cast<float*>(smem + CSQOFF);
    unsigned short* ring = reinterpret_cast<unsigned short*>(smem + RINGOFF);

    float acc[8][4];
    #pragma unroll
    for (int i = 0; i < 8; i++)
        #pragma unroll
        for (int j = 0; j < 4; j++) acc[i][j] = 0.f;

    float runmax = -1e30f;
    int cnt = 0;
    const int mypix = wbase + lane;    // valid for lane<16

    // B loader: tile nt (64 codes), k-chunk kc (128 emb) -> boff (256B rows)
    auto loadB = [&](int nt, int kc, uint32_t boff) {
        int code = t >> 2;
        const char* src = reinterpret_cast<const char*>(
            g_cbh + ((size_t)(nt * 64 + code)) * 256 + kc * 128 + (t & 3) * 32);
        uint32_t drow = sb + boff + (uint32_t)code * 256;
        uint32_t sw = (uint32_t)(code & 7);
        #pragma unroll
        for (int i = 0; i < 4; i++) {
            uint32_t u = (uint32_t)((t & 3) * 4 + i);
            uint32_t su = ((u ^ sw) & 7) | (u & 8);
            CPA16(drow + su * 16, src + i * 16);
        }
    };

    loadB(0, 0, B0OFF);
    CP_COMMIT();

    for (int c = 0; c < 128; ++c) {
        const int nt = c >> 1, kc = c & 1;
        if (c < 127) { loadB((c + 1) >> 1, (c + 1) & 1, ((c + 1) & 1) ? B1OFF : B0OFF); CP_COMMIT(); }
        if (kc == 0 && t < 64) csq_s[t] = g_csqh[nt * 64 + t];
        if (c < 127) asm volatile("cp.async.wait_group 1;" ::: "memory");
        else         asm volatile("cp.async.wait_group 0;" ::: "memory");
        __syncthreads();

        const uint32_t bbuf = sb + ((c & 1) ? B1OFF : B0OFF);
        #pragma unroll
        for (int ks = 0; ks < 8; ks++) {
            uint32_t a0, a1, a2, a3;
            {
                uint32_t unit = (uint32_t)(kc * 16 + 2 * ks + ag2);
                uint32_t su = (unit & 24) | ((unit ^ aswz) & 7);
                LDM4(a0, a1, a2, a3, abase + su * 16);
            }
            #pragma unroll
            for (int p = 0; p < 4; p++) {
                int brow = p * 16 + brp;
                uint32_t unit = (uint32_t)(2 * ks + bg1);
                uint32_t su = (unit & 8) | ((unit ^ (uint32_t)(brow & 7)) & 7);
                uint32_t b0, b1, b2, b3;
                LDM4(b0, b1, b2, b3, bbuf + (uint32_t)brow * 256 + su * 16);
                MMA16816(acc[2 * p],     a0, a1, a2, a3, b0, b1);
                MMA16816(acc[2 * p + 1], a0, a1, a2, a3, b2, b3);
            }
        }

        if (kc == 1) {
            for (int pass = (nt == 0 ? 0 : 1); pass < 2; ++pass) {
                for (int q = 0; q < 4; ++q) {
                    #pragma unroll
                    for (int idx = 0; idx < 2; ++idx) {
                        int nf = 2 * q + idx;
                        int rr = lane >> 2;
                        int cc = idx * 8 + 2 * (lane & 3);
                        stg[rr * 17 + cc]           = acc[nf][0];
                        stg[rr * 17 + cc + 1]       = acc[nf][1];
                        stg[(rr + 8) * 17 + cc]     = acc[nf][2];
                        stg[(rr + 8) * 17 + cc + 1] = acc[nf][3];
                    }
                    __syncwarp();
                    if (lane < 16) {
                        const float* row = stg + lane * 17;
                        const float* cq = csq_s + q * 16;
                        #pragma unroll 4
                        for (int j = 0; j < 16; ++j) {
                            float s = row[j] - cq[j];
                            if (pass == 0) {
                                runmax = fmaxf(runmax, s);
                            } else if (s > runmax - MARGIN) {
                                ring[mypix * 16 + (cnt & 15)] =
                                    (unsigned short)(nt * 64 + q * 16 + j);
                                cnt++;
                                runmax = fmaxf(runmax, s);
                            }
                        }
                    }
                    __syncwarp();
                }
            }
            #pragma unroll
            for (int i = 0; i < 8; i++)
                #pragma unroll
                for (int j = 0; j < 4; j++) acc[i][j] = 0.f;
        }
        __syncthreads();
    }

    if (lane < 16) {
        int pix = n_base + mypix;
        g_cnt[pix] = cnt;
        const uint32_t* r32 = reinterpret_cast<const uint32_t*>(ring + mypix * 16);
        uint32_t* cp = reinterpret_cast<uint32_t*>(g_cand[pix]);
        #pragma unroll
        for (int i = 0; i < 8; i++) cp[i] = r32[i];
    }
}

// ---------------------------------------------------------------------------
// Exact fp32 rescore. Block = 128 pixels; z staged transposed in smem.
// ---------------------------------------------------------------------------
#define SMEM_RESC (128 * 264 * 4)

__global__ void __launch_bounds__(256) k_rescore(
    const float* __restrict__ cb, const float* __restrict__ z,
    float* __restrict__ tok_out)
{
    extern __shared__ float zs[];     // [128][264]
    const int t = threadIdx.x;
    const int wid = t >> 5, lane = t & 31;
    const int n_base = blockIdx.x * 128;
    const float* zsrc = z + (size_t)(n_base >> 8) * 65536 + (n_base & 255);

    for (int kb = 0; kb < 8; kb++) {
        int e = kb * 32 + (t >> 3);
        int pg = (t & 7) * 16;
        const float4* s4 = reinterpret_cast<const float4*>(zsrc + e * 256 + pg);
        float4 v[4] = { s4[0], s4[1], s4[2], s4[3] };
        const float* vf = reinterpret_cast<const float*>(v);
        #pragma unroll
        for (int j = 0; j < 16; j++) zs[(pg + j) * 264 + e] = vf[j];
    }
    __syncthreads();

    for (int it = 0; it < 16; ++it) {
        const int pl = wid * 16 + it;
        const int pix = n_base + pl;
        const int cnt = g_cnt[pix];
        const float zq2 = g_zsq[pix];
        const float* zrow = zs + pl * 264;
        unsigned long long best = ~0ull;

        if (cnt <= 16) {
            for (int ci = 0; ci < cnt; ++ci) {
                int v = g_cand[pix][ci];
                const float* crow = cb + (size_t)v * 256;
                float part = 0.f;
                #pragma unroll
                for (int j = 0; j < 8; j++)
                    part = fmaf(zrow[lane * 8 + j], crow[lane * 8 + j], part);
                #pragma unroll
                for (int o = 16; o; o >>= 1)
                    part += __shfl_xor_sync(0xFFFFFFFFu, part, o);
                float d = (zq2 + g_csq[v]) - 2.0f * part;
                unsigned long long key = ((unsigned long long)f2ord(d) << 32) | (unsigned int)v;
                if (key < best) best = key;
            }
        } else {
            for (int v = 0; v < VOCAB; ++v) {
                const float* crow = cb + (size_t)v * 256;
                float part = 0.f;
                #pragma unroll
                for (int j = 0; j < 8; j++)
                    part = fmaf(zrow[lane * 8 + j], crow[lane * 8 + j], part);
                #pragma unroll
                for (int o = 16; o; o >>= 1)
                    part += __shfl_xor_sync(0xFFFFFFFFu, part, o);
                float d = (zq2 + g_csq[v]) - 2.0f * part;
                unsigned long long key = ((unsigned long long)f2ord(d) << 32) | (unsigned int)v;
                if (key < best) best = key;
            }
        }
        if (lane == 0) {
            int tok = (int)(best & 0xFFFFFFFFull);
            g_tok[pix] = tok;
            tok_out[pix] = (float)tok;
        }
    }
}

__global__ void k_zq(const float* __restrict__ cb, float* __restrict__ zq) {
    unsigned int g = blockIdx.x * 256 + threadIdx.x;
    int hw = g & 255, e = (g >> 8) & 255, img = g >> 16;
    zq[g] = cb[(size_t)g_tok[img * 256 + hw] * 256 + e];
}

// ---------------------------------------------------------------------------
extern "C" void kernel_launch(void* const* d_in, const int* in_sizes, int n_in,
                              void* d_out, int out_size) {
    const float* x      = (const float*)d_in[0];
    const float* cb     = (const float*)d_in[1];
    const float* pre_w  = (const float*)d_in[2];
    const float* pre_b  = (const float*)d_in[3];
    const float* post_w = (const float*)d_in[4];
    const float* post_b = (const float*)d_in[5];

    float* out   = (float*)d_out;
    float* zbuf  = out;
    float* zq    = out + 8388608;
    float* recon = out + 16777216;
    float* toks  = out + 25165824;

    static bool attr_done = false;
    if (!attr_done) {
        cudaFuncSetAttribute(k_dist_mma, cudaFuncAttributeMaxDynamicSharedMemorySize, SMEM_DIST);
        cudaFuncSetAttribute(k_rescore,  cudaFuncAttributeMaxDynamicSharedMemorySize, SMEM_RESC);
        attr_done = true;
    }

    k_init<<<1024, 128>>>(cb);                                     // 1
    k_cbh<<<4096, 256>>>(cb);                                      // 2
    k_gemm256<true><<<dim3(4, 4, IMGS), 256>>>(pre_w, pre_b, x, zbuf); // 3
    k_dist_mma<<<NPIX / 128, 256, SMEM_DIST>>>(zbuf);              // 4 (profiled slot)
    k_zsq<<<IMGS, 256>>>(zbuf);                                    // 5
    k_rescore<<<NPIX / 128, 256, SMEM_RESC>>>(cb, zbuf, toks);     // 6
    k_zq<<<8388608 / 256, 256>>>(cb, zq);                          // 7
    k_gemm256<false><<<dim3(4, 4, IMGS), 256>>>(post_w, post_b, zq, recon); // 8
}

// round 6
// speedup vs baseline: 1.2135x; 1.2135x over previous
#include <cuda_runtime.h>
#include <cuda_bf16.h>
#include <cstdint>

#define IMGS   128
#define EMB    256
#define NPIX   32768
#define VOCAB  4096
#define NRING  24

__device__ float g_csq[VOCAB];          // ||c||^2 exact fp32
__device__ float g_csqh[VOCAB];         // csq * 0.5f
__device__ int   g_tok[NPIX];
__device__ __nv_bfloat16 g_cbh[VOCAB * EMB];
__device__ unsigned short g_cand[NPIX][NRING];
__device__ int   g_cnt[NPIX];

__device__ __forceinline__ unsigned int f2ord(float f) {
    unsigned int u = __float_as_uint(f);
    return (u & 0x80000000u) ? ~u : (u | 0x80000000u);
}
__device__ __forceinline__ uint32_t smem_u32(const void* p) {
    uint32_t a;
    asm("{ .reg .u64 t; cvta.to.shared.u64 t, %1; cvt.u32.u64 %0, t; }" : "=r"(a) : "l"(p));
    return a;
}

#define LDM4(r0, r1, r2, r3, addr)                                              \
    asm volatile("ldmatrix.sync.aligned.m8n8.x4.shared.b16 {%0,%1,%2,%3}, [%4];"\
        : "=r"(r0), "=r"(r1), "=r"(r2), "=r"(r3) : "r"(addr))

#define MMA16816(d, a0, a1, a2, a3, b0, b1)                                     \
    asm volatile("mma.sync.aligned.m16n8k16.row.col.f32.bf16.bf16.f32 "         \
        "{%0,%1,%2,%3},{%4,%5,%6,%7},{%8,%9},{%0,%1,%2,%3};"                    \
        : "+f"((d)[0]), "+f"((d)[1]), "+f"((d)[2]), "+f"((d)[3])                \
        : "r"(a0), "r"(a1), "r"(a2), "r"(a3), "r"(b0), "r"(b1))

#define CPA16(dst, src)                                                         \
    asm volatile("cp.async.cg.shared.global [%0], [%1], 16;" :: "r"(dst), "l"(src))
#define CP_COMMIT() asm volatile("cp.async.commit_group;" ::: "memory")

// ---------------------------------------------------------------------------
// prep: one block per codebook row -> csq, csq/2, bf16 copy
// ---------------------------------------------------------------------------
__global__ void __launch_bounds__(256) k_prep(const float* __restrict__ cb) {
    __shared__ float red[8];
    const int r = blockIdx.x, t = threadIdx.x;
    float v = cb[r * 256 + t];
    g_cbh[r * 256 + t] = __float2bfloat16(v);
    float s = v * v;
    #pragma unroll
    for (int o = 16; o; o >>= 1) s += __shfl_down_sync(0xFFFFFFFFu, s, o);
    if ((t & 31) == 0) red[t >> 5] = s;
    __syncthreads();
    if (t == 0) {
        float tot = 0.f;
        #pragma unroll
        for (int i = 0; i < 8; i++) tot += red[i];
        g_csq[r] = tot; g_csqh[r] = 0.5f * tot;
    }
}

// ---------------------------------------------------------------------------
// fp32 256x256x256 GEMM (pre/post)
// ---------------------------------------------------------------------------
template<bool XFORM>
__global__ void __launch_bounds__(256) k_gemm256(
    const float* __restrict__ W, const float* __restrict__ bias,
    const float* __restrict__ In, float* __restrict__ Out)
{
    __shared__ float Ws[16][68];
    __shared__ float Bs[16][64];
    const int img = blockIdx.z;
    const int m0 = blockIdx.y * 64, n0 = blockIdx.x * 64;
    const float* in = In + (size_t)img * 65536;
    float* out = Out + (size_t)img * 65536;
    const int t = threadIdx.x;
    const int ty = t >> 4, tx = t & 15;
    float acc[4][4] = {};
    for (int k0 = 0; k0 < 256; k0 += 16) {
        {
            int row = t >> 2, c4 = (t & 3) * 4;
            float4 w4 = *reinterpret_cast<const float4*>(&W[(m0 + row) * 256 + k0 + c4]);
            Ws[c4 + 0][row] = w4.x; Ws[c4 + 1][row] = w4.y;
            Ws[c4 + 2][row] = w4.z; Ws[c4 + 3][row] = w4.w;
        }
        {
            int kk = t >> 4, n4 = (t & 15) * 4;
            float4 b4 = *reinterpret_cast<const float4*>(&in[(k0 + kk) * 256 + n0 + n4]);
            if (XFORM) {
                b4.x = 2.f * b4.x - 1.f; b4.y = 2.f * b4.y - 1.f;
                b4.z = 2.f * b4.z - 1.f; b4.w = 2.f * b4.w - 1.f;
            }
            *reinterpret_cast<float4*>(&Bs[kk][n4]) = b4;
        }
        __syncthreads();
        #pragma unroll
        for (int kk = 0; kk < 16; kk++) {
            float a[4], b[4];
            *reinterpret_cast<float4*>(a) = *reinterpret_cast<float4*>(&Ws[kk][ty * 4]);
            *reinterpret_cast<float4*>(b) = *reinterpret_cast<float4*>(&Bs[kk][tx * 4]);
            #pragma unroll
            for (int i = 0; i < 4; i++)
                #pragma unroll
                for (int j = 0; j < 4; j++)
                    acc[i][j] += a[i] * b[j];
        }
        __syncthreads();
    }
    #pragma unroll
    for (int i = 0; i < 4; i++) {
        int m = m0 + ty * 4 + i;
        float bm = bias[m];
        float4 o;
        o.x = acc[i][0] + bm; o.y = acc[i][1] + bm;
        o.z = acc[i][2] + bm; o.w = acc[i][3] + bm;
        *reinterpret_cast<float4*>(&out[m * 256 + n0 + tx * 4]) = o;
    }
}

// ---------------------------------------------------------------------------
// bf16 mma.sync score GEMM + per-pixel serial prune, ring of 24 in SMEM.
// SMEM: A 64KB | B0 16KB | B1 16KB | stg 8x1088 | csq 256B | ring 6KB
// ---------------------------------------------------------------------------
#define AOFF      0
#define B0OFF     65536
#define B1OFF     81920
#define STGOFF    98304
#define CSQOFF    107008
#define RINGOFF   107264
#define SMEM_DIST 113408
#define MARGIN    2.5e-5f

__global__ void __launch_bounds__(256, 2) k_dist_mma(const float* __restrict__ z) {
    extern __shared__ char smem[];
    const uint32_t sb = smem_u32(smem);
    const int t = threadIdx.x;
    const int wid = t >> 5, lane = t & 31;
    const int n_base = blockIdx.x * 128;

    // ---- A build: z (fp32 [e][pix]) -> bf16 swizzled [pix][e] (scratch = B0) ----
    {
        const float* zsrc = z + (size_t)(n_base >> 8) * 65536 + (n_base & 255);
        float* scr = reinterpret_cast<float*>(smem + B0OFF);   // 32e x 128pix fp32
        for (int kb = 0; kb < 8; kb++) {
            int e_l = t >> 3;
            int pg = (t & 7) * 16;
            const float4* s4 = reinterpret_cast<const float4*>(zsrc + (kb * 32 + e_l) * 256 + pg);
            float4 v0 = s4[0], v1 = s4[1], v2 = s4[2], v3 = s4[3];
            float4* d4 = reinterpret_cast<float4*>(scr + e_l * 128 + pg);
            d4[0] = v0; d4[1] = v1; d4[2] = v2; d4[3] = v3;
            __syncthreads();
            int pix = t & 127, half = t >> 7;
            #pragma unroll
            for (int jj = 0; jj < 8; jj++) {
                int el0 = (half * 8 + jj) * 2;
                float a = scr[el0 * 128 + pix], b = scr[(el0 + 1) * 128 + pix];
                uint32_t u;
                asm("cvt.rn.bf16x2.f32 %0, %1, %2;" : "=r"(u) : "f"(b), "f"(a));
                int eg = kb * 32 + el0;
                uint32_t unit = (uint32_t)(eg >> 3);
                uint32_t su = (unit & 24) | ((unit ^ (uint32_t)(pix & 7)) & 7);
                uint32_t addr = sb + AOFF + (uint32_t)pix * 512 + su * 16 + (eg & 7) * 2;
                asm volatile("st.shared.b32 [%0], %1;" :: "r"(addr), "r"(u) : "memory");
            }
            __syncthreads();
        }
    }

    const int wbase = wid * 16;
    const int arow = wbase + (lane & 7) + ((lane >> 3) & 1) * 8;
    const uint32_t aswz = (uint32_t)(arow & 7);
    const uint32_t abase = sb + AOFF + (uint32_t)arow * 512;
    const int ag2 = lane >> 4;
    const int brp = ((lane >> 4) & 1) * 8 + (lane & 7);
    const int bg1 = (lane >> 3) & 1;
    float* stg = reinterpret_cast<float*>(smem + STGOFF + wid * 1088);
    float* csq_s = reinterpret_cast<float*>(smem + CSQOFF);
    unsigned short* ring = reinterpret_cast<unsigned short*>(smem + RINGOFF);

    float acc[8][4];
    #pragma unroll
    for (int i = 0; i < 8; i++)
        #pragma unroll
        for (int j = 0; j < 4; j++) acc[i][j] = 0.f;

    float runmax = -1e30f;
    int cnt = 0;
    const int mypix = wbase + lane;    // valid for lane<16

    auto loadB = [&](int nt, int kc, uint32_t boff) {
        int code = t >> 2;
        const char* src = reinterpret_cast<const char*>(
            g_cbh + ((size_t)(nt * 64 + code)) * 256 + kc * 128 + (t & 3) * 32);
        uint32_t drow = sb + boff + (uint32_t)code * 256;
        uint32_t sw = (uint32_t)(code & 7);
        #pragma unroll
        for (int i = 0; i < 4; i++) {
            uint32_t u = (uint32_t)((t & 3) * 4 + i);
            uint32_t su = ((u ^ sw) & 7) | (u & 8);
            CPA16(drow + su * 16, src + i * 16);
        }
    };

    loadB(0, 0, B0OFF);
    CP_COMMIT();

    for (int c = 0; c < 128; ++c) {
        const int nt = c >> 1, kc = c & 1;
        if (c < 127) { loadB((c + 1) >> 1, (c + 1) & 1, ((c + 1) & 1) ? B1OFF : B0OFF); CP_COMMIT(); }
        if (kc == 0 && t < 64) csq_s[t] = g_csqh[nt * 64 + t];
        if (c < 127) asm volatile("cp.async.wait_group 1;" ::: "memory");
        else         asm volatile("cp.async.wait_group 0;" ::: "memory");
        __syncthreads();

        const uint32_t bbuf = sb + ((c & 1) ? B1OFF : B0OFF);
        #pragma unroll
        for (int ks = 0; ks < 8; ks++) {
            uint32_t a0, a1, a2, a3;
            {
                uint32_t unit = (uint32_t)(kc * 16 + 2 * ks + ag2);
                uint32_t su = (unit & 24) | ((unit ^ aswz) & 7);
                LDM4(a0, a1, a2, a3, abase + su * 16);
            }
            #pragma unroll
            for (int p = 0; p < 4; p++) {
                int brow = p * 16 + brp;
                uint32_t unit = (uint32_t)(2 * ks + bg1);
                uint32_t su = (unit & 8) | ((unit ^ (uint32_t)(brow & 7)) & 7);
                uint32_t b0, b1, b2, b3;
                LDM4(b0, b1, b2, b3, bbuf + (uint32_t)brow * 256 + su * 16);
                MMA16816(acc[2 * p],     a0, a1, a2, a3, b0, b1);
                MMA16816(acc[2 * p + 1], a0, a1, a2, a3, b2, b3);
            }
        }

        if (kc == 1) {
            for (int q = 0; q < 4; ++q) {
                #pragma unroll
                for (int idx = 0; idx < 2; ++idx) {
                    int nf = 2 * q + idx;
                    int rr = lane >> 2;
                    int cc = idx * 8 + 2 * (lane & 3);
                    stg[rr * 17 + cc]           = acc[nf][0];
                    stg[rr * 17 + cc + 1]       = acc[nf][1];
                    stg[(rr + 8) * 17 + cc]     = acc[nf][2];
                    stg[(rr + 8) * 17 + cc + 1] = acc[nf][3];
                }
                __syncwarp();
                if (lane < 16) {
                    const float* row = stg + lane * 17;
                    const float* cq = csq_s + q * 16;
                    #pragma unroll 4
                    for (int j = 0; j < 16; ++j) {
                        float s = row[j] - cq[j];
                        if (s > runmax - MARGIN) {
                            ring[mypix * NRING + (cnt % NRING)] =
                                (unsigned short)(nt * 64 + q * 16 + j);
                            cnt++;
                            runmax = fmaxf(runmax, s);
                        }
                    }
                }
                __syncwarp();
            }
            #pragma unroll
            for (int i = 0; i < 8; i++)
                #pragma unroll
                for (int j = 0; j < 4; j++) acc[i][j] = 0.f;
        }
        __syncthreads();
    }

    if (lane < 16) {
        int pix = n_base + mypix;
        g_cnt[pix] = cnt;
        const uint32_t* r32 = reinterpret_cast<const uint32_t*>(ring + mypix * NRING);
        uint32_t* cp = reinterpret_cast<uint32_t*>(g_cand[pix]);
        #pragma unroll
        for (int i = 0; i < NRING / 2; i++) cp[i] = r32[i];
    }
}

// ---------------------------------------------------------------------------
// Exact fp32 rescore (+ inline zsq, sequential order). Block = 128 pixels.
// ---------------------------------------------------------------------------
#define SMEM_RESC (128 * 264 * 4 + 512)

__global__ void __launch_bounds__(256) k_rescore(
    const float* __restrict__ cb, const float* __restrict__ z,
    float* __restrict__ tok_out)
{
    extern __shared__ float zs[];     // [128][264] + zsq[128]
    float* zsq_s = zs + 128 * 264;
    const int t = threadIdx.x;
    const int wid = t >> 5, lane = t & 31;
    const int n_base = blockIdx.x * 128;
    const float* zsrc = z + (size_t)(n_base >> 8) * 65536 + (n_base & 255);

    for (int kb = 0; kb < 8; kb++) {
        int e = kb * 32 + (t >> 3);
        int pg = (t & 7) * 16;
        const float4* s4 = reinterpret_cast<const float4*>(zsrc + e * 256 + pg);
        float4 v[4] = { s4[0], s4[1], s4[2], s4[3] };
        const float* vf = reinterpret_cast<const float*>(v);
        #pragma unroll
        for (int j = 0; j < 16; j++) zs[(pg + j) * 264 + e] = vf[j];
    }
    __syncthreads();

    // zsq: sequential over e (matches reference-order recipe), pixels 0..127
    if (t < 128) {
        const float* zr = zs + t * 264;
        float s = 0.f;
        #pragma unroll 8
        for (int e = 0; e < 256; e++) { float v = zr[e]; s = fmaf(v, v, s); }
        zsq_s[t] = s;
    }
    __syncthreads();

    for (int it = 0; it < 16; ++it) {
        const int pl = wid * 16 + it;
        const int pix = n_base + pl;
        const int cnt = g_cnt[pix];
        const float zq2 = zsq_s[pl];
        const float* zrow = zs + pl * 264;
        unsigned long long best = ~0ull;

        if (cnt <= NRING) {
            for (int ci = 0; ci < cnt; ++ci) {
                int v = g_cand[pix][ci];
                const float* crow = cb + (size_t)v * 256;
                float4 za = *reinterpret_cast<const float4*>(zrow + lane * 8);
                float4 zb = *reinterpret_cast<const float4*>(zrow + lane * 8 + 4);
                float4 ca = *reinterpret_cast<const float4*>(crow + lane * 8);
                float4 cbv = *reinterpret_cast<const float4*>(crow + lane * 8 + 4);
                float part = za.x * ca.x;
                part = fmaf(za.y, ca.y, part);
                part = fmaf(za.z, ca.z, part);
                part = fmaf(za.w, ca.w, part);
                part = fmaf(zb.x, cbv.x, part);
                part = fmaf(zb.y, cbv.y, part);
                part = fmaf(zb.z, cbv.z, part);
                part = fmaf(zb.w, cbv.w, part);
                #pragma unroll
                for (int o = 16; o; o >>= 1)
                    part += __shfl_xor_sync(0xFFFFFFFFu, part, o);
                float d = (zq2 + g_csq[v]) - 2.0f * part;
                unsigned long long key = ((unsigned long long)f2ord(d) << 32) | (unsigned int)v;
                if (key < best) best = key;
            }
        } else {
            for (int v = 0; v < VOCAB; ++v) {
                const float* crow = cb + (size_t)v * 256;
                float4 za = *reinterpret_cast<const float4*>(zrow + lane * 8);
                float4 zb = *reinterpret_cast<const float4*>(zrow + lane * 8 + 4);
                float4 ca = *reinterpret_cast<const float4*>(crow + lane * 8);
                float4 cbv = *reinterpret_cast<const float4*>(crow + lane * 8 + 4);
                float part = za.x * ca.x;
                part = fmaf(za.y, ca.y, part);
                part = fmaf(za.z, ca.z, part);
                part = fmaf(za.w, ca.w, part);
                part = fmaf(zb.x, cbv.x, part);
                part = fmaf(zb.y, cbv.y, part);
                part = fmaf(zb.z, cbv.z, part);
                part = fmaf(zb.w, cbv.w, part);
                #pragma unroll
                for (int o = 16; o; o >>= 1)
                    part += __shfl_xor_sync(0xFFFFFFFFu, part, o);
                float d = (zq2 + g_csq[v]) - 2.0f * part;
                unsigned long long key = ((unsigned long long)f2ord(d) << 32) | (unsigned int)v;
                if (key < best) best = key;
            }
        }
        if (lane == 0) {
            int tok = (int)(best & 0xFFFFFFFFull);
            g_tok[pix] = tok;
            tok_out[pix] = (float)tok;
        }
    }
}

__global__ void k_zq(const float* __restrict__ cb, float* __restrict__ zq) {
    unsigned int g = blockIdx.x * 256 + threadIdx.x;
    int hw = g & 255, e = (g >> 8) & 255, img = g >> 16;
    zq[g] = cb[(size_t)g_tok[img * 256 + hw] * 256 + e];
}

// ---------------------------------------------------------------------------
extern "C" void kernel_launch(void* const* d_in, const int* in_sizes, int n_in,
                              void* d_out, int out_size) {
    const float* x      = (const float*)d_in[0];
    const float* cb     = (const float*)d_in[1];
    const float* pre_w  = (const float*)d_in[2];
    const float* pre_b  = (const float*)d_in[3];
    const float* post_w = (const float*)d_in[4];
    const float* post_b = (const float*)d_in[5];

    float* out   = (float*)d_out;
    float* zbuf  = out;
    float* zq    = out + 8388608;
    float* recon = out + 16777216;
    float* toks  = out + 25165824;

    static bool attr_done = false;
    if (!attr_done) {
        cudaFuncSetAttribute(k_dist_mma, cudaFuncAttributeMaxDynamicSharedMemorySize, SMEM_DIST);
        cudaFuncSetAttribute(k_rescore,  cudaFuncAttributeMaxDynamicSharedMemorySize, SMEM_RESC);
        attr_done = true;
    }

    k_prep<<<VOCAB, 256>>>(cb);                                        // 1
    k_gemm256<true><<<dim3(4, 4, IMGS), 256>>>(pre_w, pre_b, x, zbuf); // 2
    k_dist_mma<<<NPIX / 128, 256, SMEM_DIST>>>(zbuf);                  // 3
    k_rescore<<<NPIX / 128, 256, SMEM_RESC>>>(cb, zbuf, toks);         // 4 (profiled)
    k_zq<<<8388608 / 256, 256>>>(cb, zq);                              // 5
    k_gemm256<false><<<dim3(4, 4, IMGS), 256>>>(post_w, post_b, zq, recon); // 6
}

// round 7
// speedup vs baseline: 1.5442x; 1.2725x over previous
#include <cuda_runtime.h>
#include <cuda_bf16.h>
#include <cstdint>

#define IMGS   128
#define EMB    256
#define NPIX   32768
#define VOCAB  4096
#define NLRING 12          // per-(lane,row) ring capacity
#define NC_MAX 48          // max candidates per pixel (4 lanes x 12)

__device__ float g_csq[VOCAB];
__device__ float g_csqh[VOCAB];
__device__ int   g_tok[NPIX];
__device__ __nv_bfloat16 g_cbh[VOCAB * EMB];
__device__ unsigned short g_cand[NPIX][NC_MAX];
__device__ int   g_cnt[NPIX];
__device__ int   g_nfb;
__device__ int   g_fblist[NPIX];

__device__ __forceinline__ unsigned int f2ord(float f) {
    unsigned int u = __float_as_uint(f);
    return (u & 0x80000000u) ? ~u : (u | 0x80000000u);
}
__device__ __forceinline__ uint32_t smem_u32(const void* p) {
    uint32_t a;
    asm("{ .reg .u64 t; cvta.to.shared.u64 t, %1; cvt.u32.u64 %0, t; }" : "=r"(a) : "l"(p));
    return a;
}

#define LDM4(r0, r1, r2, r3, addr)                                              \
    asm volatile("ldmatrix.sync.aligned.m8n8.x4.shared.b16 {%0,%1,%2,%3}, [%4];"\
        : "=r"(r0), "=r"(r1), "=r"(r2), "=r"(r3) : "r"(addr))

#define MMA16816(d, a0, a1, a2, a3, b0, b1)                                     \
    asm volatile("mma.sync.aligned.m16n8k16.row.col.f32.bf16.bf16.f32 "         \
        "{%0,%1,%2,%3},{%4,%5,%6,%7},{%8,%9},{%0,%1,%2,%3};"                    \
        : "+f"((d)[0]), "+f"((d)[1]), "+f"((d)[2]), "+f"((d)[3])                \
        : "r"(a0), "r"(a1), "r"(a2), "r"(a3), "r"(b0), "r"(b1))

#define CPA16(dst, src)                                                         \
    asm volatile("cp.async.cg.shared.global [%0], [%1], 16;" :: "r"(dst), "l"(src))
#define CP_COMMIT() asm volatile("cp.async.commit_group;" ::: "memory")

// ---------------------------------------------------------------------------
__global__ void __launch_bounds__(256) k_prep(const float* __restrict__ cb) {
    __shared__ float red[8];
    const int r = blockIdx.x, t = threadIdx.x;
    float v = cb[r * 256 + t];
    g_cbh[r * 256 + t] = __float2bfloat16(v);
    float s = v * v;
    #pragma unroll
    for (int o = 16; o; o >>= 1) s += __shfl_down_sync(0xFFFFFFFFu, s, o);
    if ((t & 31) == 0) red[t >> 5] = s;
    __syncthreads();
    if (t == 0) {
        float tot = 0.f;
        #pragma unroll
        for (int i = 0; i < 8; i++) tot += red[i];
        g_csq[r] = tot; g_csqh[r] = 0.5f * tot;
    }
}

__global__ void k_zero() { if (threadIdx.x == 0) g_nfb = 0; }

// ---------------------------------------------------------------------------
// fp32 256x256x256 GEMM (pre/post)
// ---------------------------------------------------------------------------
template<bool XFORM>
__global__ void __launch_bounds__(256) k_gemm256(
    const float* __restrict__ W, const float* __restrict__ bias,
    const float* __restrict__ In, float* __restrict__ Out)
{
    __shared__ float Ws[16][68];
    __shared__ float Bs[16][64];
    const int img = blockIdx.z;
    const int m0 = blockIdx.y * 64, n0 = blockIdx.x * 64;
    const float* in = In + (size_t)img * 65536;
    float* out = Out + (size_t)img * 65536;
    const int t = threadIdx.x;
    const int ty = t >> 4, tx = t & 15;
    float acc[4][4] = {};
    for (int k0 = 0; k0 < 256; k0 += 16) {
        {
            int row = t >> 2, c4 = (t & 3) * 4;
            float4 w4 = *reinterpret_cast<const float4*>(&W[(m0 + row) * 256 + k0 + c4]);
            Ws[c4 + 0][row] = w4.x; Ws[c4 + 1][row] = w4.y;
            Ws[c4 + 2][row] = w4.z; Ws[c4 + 3][row] = w4.w;
        }
        {
            int kk = t >> 4, n4 = (t & 15) * 4;
            float4 b4 = *reinterpret_cast<const float4*>(&in[(k0 + kk) * 256 + n0 + n4]);
            if (XFORM) {
                b4.x = 2.f * b4.x - 1.f; b4.y = 2.f * b4.y - 1.f;
                b4.z = 2.f * b4.z - 1.f; b4.w = 2.f * b4.w - 1.f;
            }
            *reinterpret_cast<float4*>(&Bs[kk][n4]) = b4;
        }
        __syncthreads();
        #pragma unroll
        for (int kk = 0; kk < 16; kk++) {
            float a[4], b[4];
            *reinterpret_cast<float4*>(a) = *reinterpret_cast<float4*>(&Ws[kk][ty * 4]);
            *reinterpret_cast<float4*>(b) = *reinterpret_cast<float4*>(&Bs[kk][tx * 4]);
            #pragma unroll
            for (int i = 0; i < 4; i++)
                #pragma unroll
                for (int j = 0; j < 4; j++)
                    acc[i][j] += a[i] * b[j];
        }
        __syncthreads();
    }
    #pragma unroll
    for (int i = 0; i < 4; i++) {
        int m = m0 + ty * 4 + i;
        float bm = bias[m];
        float4 o;
        o.x = acc[i][0] + bm; o.y = acc[i][1] + bm;
        o.z = acc[i][2] + bm; o.w = acc[i][3] + bm;
        *reinterpret_cast<float4*>(&out[m * 256 + n0 + tx * 4]) = o;
    }
}

// ---------------------------------------------------------------------------
// bf16 mma.sync score GEMM, register-local prune into per-lane smem rings.
// SMEM: A 64KB | B0 16KB | B1 16KB | csq 256B | rings 12KB  = 108.25KB
// ---------------------------------------------------------------------------
#define AOFF      0
#define B0OFF     65536
#define B1OFF     81920
#define CSQOFF    98304
#define RINGOFF   98560
#define SMEM_DIST 110848
#define MARGIN    2.5e-5f

__global__ void __launch_bounds__(256, 2) k_dist_mma(const float* __restrict__ z) {
    extern __shared__ char smem[];
    const uint32_t sb = smem_u32(smem);
    const int t = threadIdx.x;
    const int wid = t >> 5, lane = t & 31;
    const int n_base = blockIdx.x * 128;

    // ---- A build: z (fp32 [e][pix]) -> bf16 swizzled [pix][e] (scratch = B0) ----
    {
        const float* zsrc = z + (size_t)(n_base >> 8) * 65536 + (n_base & 255);
        float* scr = reinterpret_cast<float*>(smem + B0OFF);   // 32e x 128pix fp32
        for (int kb = 0; kb < 8; kb++) {
            int e_l = t >> 3;
            int pg = (t & 7) * 16;
            const float4* s4 = reinterpret_cast<const float4*>(zsrc + (kb * 32 + e_l) * 256 + pg);
            float4 v0 = s4[0], v1 = s4[1], v2 = s4[2], v3 = s4[3];
            float4* d4 = reinterpret_cast<float4*>(scr + e_l * 128 + pg);
            d4[0] = v0; d4[1] = v1; d4[2] = v2; d4[3] = v3;
            __syncthreads();
            int pix = t & 127, half = t >> 7;
            #pragma unroll
            for (int jj = 0; jj < 8; jj++) {
                int el0 = (half * 8 + jj) * 2;
                float a = scr[el0 * 128 + pix], b = scr[(el0 + 1) * 128 + pix];
                uint32_t u;
                asm("cvt.rn.bf16x2.f32 %0, %1, %2;" : "=r"(u) : "f"(b), "f"(a));
                int eg = kb * 32 + el0;
                uint32_t unit = (uint32_t)(eg >> 3);
                uint32_t su = (unit & 24) | ((unit ^ (uint32_t)(pix & 7)) & 7);
                uint32_t addr = sb + AOFF + (uint32_t)pix * 512 + su * 16 + (eg & 7) * 2;
                asm volatile("st.shared.b32 [%0], %1;" :: "r"(addr), "r"(u) : "memory");
            }
            __syncthreads();
        }
    }

    const int wbase = wid * 16;
    const int arow = wbase + (lane & 7) + ((lane >> 3) & 1) * 8;
    const uint32_t aswz = (uint32_t)(arow & 7);
    const uint32_t abase = sb + AOFF + (uint32_t)arow * 512;
    const int ag2 = lane >> 4;
    const int brp = ((lane >> 4) & 1) * 8 + (lane & 7);
    const int bg1 = (lane >> 3) & 1;
    float* csq_s = reinterpret_cast<float*>(smem + CSQOFF);
    unsigned short* ringp =
        reinterpret_cast<unsigned short*>(smem + RINGOFF) + (wid * 32 + lane) * 24;
    // slots [0,12) = lo row, [12,24) = hi row

    float acc[8][4];
    #pragma unroll
    for (int i = 0; i < 8; i++)
        #pragma unroll
        for (int j = 0; j < 4; j++) acc[i][j] = 0.f;

    float rmx_lo = -1e30f, rmx_hi = -1e30f;
    int cl = 0, ch = 0;

    auto loadB = [&](int nt, int kc, uint32_t boff) {
        int code = t >> 2;
        const char* src = reinterpret_cast<const char*>(
            g_cbh + ((size_t)(nt * 64 + code)) * 256 + kc * 128 + (t & 3) * 32);
        uint32_t drow = sb + boff + (uint32_t)code * 256;
        uint32_t sw = (uint32_t)(code & 7);
        #pragma unroll
        for (int i = 0; i < 4; i++) {
            uint32_t u = (uint32_t)((t & 3) * 4 + i);
            uint32_t su = ((u ^ sw) & 7) | (u & 8);
            CPA16(drow + su * 16, src + i * 16);
        }
    };

    loadB(0, 0, B0OFF);
    CP_COMMIT();

    for (int c = 0; c < 128; ++c) {
        const int nt = c >> 1, kc = c & 1;
        if (c < 127) { loadB((c + 1) >> 1, (c + 1) & 1, ((c + 1) & 1) ? B1OFF : B0OFF); CP_COMMIT(); }
        if (kc == 0 && t < 64) csq_s[t] = g_csqh[nt * 64 + t];
        if (c < 127) asm volatile("cp.async.wait_group 1;" ::: "memory");
        else         asm volatile("cp.async.wait_group 0;" ::: "memory");
        __syncthreads();

        const uint32_t bbuf = sb + ((c & 1) ? B1OFF : B0OFF);
        #pragma unroll
        for (int ks = 0; ks < 8; ks++) {
            uint32_t a0, a1, a2, a3;
            {
                uint32_t unit = (uint32_t)(kc * 16 + 2 * ks + ag2);
                uint32_t su = (unit & 24) | ((unit ^ aswz) & 7);
                LDM4(a0, a1, a2, a3, abase + su * 16);
            }
            #pragma unroll
            for (int p = 0; p < 4; p++) {
                int brow = p * 16 + brp;
                uint32_t unit = (uint32_t)(2 * ks + bg1);
                uint32_t su = (unit & 8) | ((unit ^ (uint32_t)(brow & 7)) & 7);
                uint32_t b0, b1, b2, b3;
                LDM4(b0, b1, b2, b3, bbuf + (uint32_t)brow * 256 + su * 16);
                MMA16816(acc[2 * p],     a0, a1, a2, a3, b0, b1);
                MMA16816(acc[2 * p + 1], a0, a1, a2, a3, b2, b3);
            }
        }

        if (kc == 1) {
            const int vtile = nt * 64;
            #pragma unroll
            for (int q = 0; q < 4; ++q) {
                const int cbase = q * 16 + 2 * (lane & 3);
                float2 cq0 = *reinterpret_cast<const float2*>(csq_s + cbase);
                float2 cq1 = *reinterpret_cast<const float2*>(csq_s + cbase + 8);
                const int nf0 = 2 * q, nf1 = 2 * q + 1;
                float s;
                // low row (lane>>2)
                s = acc[nf0][0] - cq0.x;
                if (s > rmx_lo - MARGIN) { if (cl < NLRING) ringp[cl] = (unsigned short)(vtile + cbase);     cl++; rmx_lo = fmaxf(rmx_lo, s); }
                s = acc[nf0][1] - cq0.y;
                if (s > rmx_lo - MARGIN) { if (cl < NLRING) ringp[cl] = (unsigned short)(vtile + cbase + 1); cl++; rmx_lo = fmaxf(rmx_lo, s); }
                s = acc[nf1][0] - cq1.x;
                if (s > rmx_lo - MARGIN) { if (cl < NLRING) ringp[cl] = (unsigned short)(vtile + cbase + 8); cl++; rmx_lo = fmaxf(rmx_lo, s); }
                s = acc[nf1][1] - cq1.y;
                if (s > rmx_lo - MARGIN) { if (cl < NLRING) ringp[cl] = (unsigned short)(vtile + cbase + 9); cl++; rmx_lo = fmaxf(rmx_lo, s); }
                // high row (lane>>2)+8
                s = acc[nf0][2] - cq0.x;
                if (s > rmx_hi - MARGIN) { if (ch < NLRING) ringp[12 + ch] = (unsigned short)(vtile + cbase);     ch++; rmx_hi = fmaxf(rmx_hi, s); }
                s = acc[nf0][3] - cq0.y;
                if (s > rmx_hi - MARGIN) { if (ch < NLRING) ringp[12 + ch] = (unsigned short)(vtile + cbase + 1); ch++; rmx_hi = fmaxf(rmx_hi, s); }
                s = acc[nf1][2] - cq1.x;
                if (s > rmx_hi - MARGIN) { if (ch < NLRING) ringp[12 + ch] = (unsigned short)(vtile + cbase + 8); ch++; rmx_hi = fmaxf(rmx_hi, s); }
                s = acc[nf1][3] - cq1.y;
                if (s > rmx_hi - MARGIN) { if (ch < NLRING) ringp[12 + ch] = (unsigned short)(vtile + cbase + 9); ch++; rmx_hi = fmaxf(rmx_hi, s); }
                // quad sync of running maxima
                rmx_lo = fmaxf(rmx_lo, __shfl_xor_sync(0xFFFFFFFFu, rmx_lo, 1));
                rmx_lo = fmaxf(rmx_lo, __shfl_xor_sync(0xFFFFFFFFu, rmx_lo, 2));
                rmx_hi = fmaxf(rmx_hi, __shfl_xor_sync(0xFFFFFFFFu, rmx_hi, 1));
                rmx_hi = fmaxf(rmx_hi, __shfl_xor_sync(0xFFFFFFFFu, rmx_hi, 2));
            }
            #pragma unroll
            for (int i = 0; i < 8; i++)
                #pragma unroll
                for (int j = 0; j < 4; j++) acc[i][j] = 0.f;
        }
        __syncthreads();
    }

    // ---- merge per pixel: quad prefix over capped counts ----
    const unsigned qb = lane & ~3u;
    const int liq = lane & 3;
    #pragma unroll
    for (int rowsel = 0; rowsel < 2; ++rowsel) {
        int mycnt = rowsel ? ch : cl;
        int l0 = __shfl_sync(0xFFFFFFFFu, mycnt, qb + 0);
        int l1 = __shfl_sync(0xFFFFFFFFu, mycnt, qb + 1);
        int l2 = __shfl_sync(0xFFFFFFFFu, mycnt, qb + 2);
        int l3 = __shfl_sync(0xFFFFFFFFu, mycnt, qb + 3);
        int m0 = min(l0, NLRING), m1 = min(l1, NLRING),
            m2 = min(l2, NLRING), m3 = min(l3, NLRING);
        int tot = m0 + m1 + m2 + m3;
        bool ovf = (l0 > NLRING) | (l1 > NLRING) | (l2 > NLRING) | (l3 > NLRING);
        int pre = (liq > 0 ? m0 : 0) + (liq > 1 ? m1 : 0) + (liq > 2 ? m2 : 0);
        int pix = n_base + wbase + (lane >> 2) + rowsel * 8;
        if (liq == 0) g_cnt[pix] = ovf ? 1000 : tot;
        int myc = min(mycnt, NLRING);
        const unsigned short* rp = ringp + rowsel * 12;
        for (int i = 0; i < myc; ++i) g_cand[pix][pre + i] = rp[i];
    }
}

// ---------------------------------------------------------------------------
// Rescore: warp-per-pixel, exact fp32; overflow pixels -> fallback list.
// ---------------------------------------------------------------------------
__global__ void __launch_bounds__(256) k_rescore(
    const float* __restrict__ cb, const float* __restrict__ z,
    float* __restrict__ tok_out)
{
    __shared__ float zs[8][260];
    __shared__ float zsq_s[8];
    const int t = threadIdx.x;
    const int wid = t >> 5, lane = t & 31;
    const int n_base = blockIdx.x * 8;
    const float* zsrc = z + (size_t)(n_base >> 8) * 65536 + (n_base & 255);

    for (int idx = t; idx < 2048; idx += 256) {
        int e = idx >> 3, p = idx & 7;
        zs[p][e] = zsrc[e * 256 + p];
    }
    __syncthreads();
    if (t < 8) {
        const float* zr = zs[t];
        float s = 0.f;
        #pragma unroll 8
        for (int e = 0; e < 256; e++) { float v = zr[e]; s = fmaf(v, v, s); }
        zsq_s[t] = s;
    }
    __syncthreads();

    const int pix = n_base + wid;
    const int cnt = g_cnt[pix];
    const float zq2 = zsq_s[wid];
    const float* zrow = zs[wid];

    if (cnt <= NC_MAX) {
        unsigned long long best = ~0ull;
        for (int ci = 0; ci < cnt; ++ci) {
            int v = g_cand[pix][ci];
            const float* crow = cb + (size_t)v * 256;
            float4 za = *reinterpret_cast<const float4*>(zrow + lane * 8);
            float4 zb = *reinterpret_cast<const float4*>(zrow + lane * 8 + 4);
            float4 ca = *reinterpret_cast<const float4*>(crow + lane * 8);
            float4 cbv = *reinterpret_cast<const float4*>(crow + lane * 8 + 4);
            float part = za.x * ca.x;
            part = fmaf(za.y, ca.y, part);
            part = fmaf(za.z, ca.z, part);
            part = fmaf(za.w, ca.w, part);
            part = fmaf(zb.x, cbv.x, part);
            part = fmaf(zb.y, cbv.y, part);
            part = fmaf(zb.z, cbv.z, part);
            part = fmaf(zb.w, cbv.w, part);
            #pragma unroll
            for (int o = 16; o; o >>= 1)
                part += __shfl_xor_sync(0xFFFFFFFFu, part, o);
            float d = (zq2 + g_csq[v]) - 2.0f * part;
            unsigned long long key = ((unsigned long long)f2ord(d) << 32) | (unsigned int)v;
            if (key < best) best = key;
        }
        if (lane == 0) {
            int tok = (int)(best & 0xFFFFFFFFull);
            g_tok[pix] = tok;
            tok_out[pix] = (float)tok;
        }
    } else if (lane == 0) {
        int idx = atomicAdd(&g_nfb, 1);
        g_fblist[idx] = pix;
    }
}

// ---------------------------------------------------------------------------
// Fallback: block-per-pixel full scan, thread-per-code.
// ---------------------------------------------------------------------------
__global__ void __launch_bounds__(256) k_fallback(
    const float* __restrict__ cb, const float* __restrict__ z,
    float* __restrict__ tok_out)
{
    __shared__ float zr[256];
    __shared__ float zsq_sh;
    __shared__ unsigned long long wmin[8];
    const int t = threadIdx.x;
    const int wid = t >> 5, lane = t & 31;
    const int n = g_nfb;

    for (int i = blockIdx.x; i < n; i += gridDim.x) {
        const int pix = g_fblist[i];
        const float* zsrc = z + (size_t)(pix >> 8) * 65536 + (pix & 255);
        zr[t] = zsrc[t * 256];
        __syncthreads();
        if (t == 0) {
            float s = 0.f;
            #pragma unroll 8
            for (int e = 0; e < 256; e++) { float v = zr[e]; s = fmaf(v, v, s); }
            zsq_sh = s;
        }
        __syncthreads();
        const float zq2 = zsq_sh;
        unsigned long long best = ~0ull;
        for (int pass = 0; pass < 16; ++pass) {
            int v = pass * 256 + t;
            const float* crow = cb + (size_t)v * 256;
            float a0 = 0.f, a1 = 0.f, a2 = 0.f, a3 = 0.f;
            #pragma unroll 8
            for (int e = 0; e < 256; e += 4) {
                a0 = fmaf(zr[e],     crow[e],     a0);
                a1 = fmaf(zr[e + 1], crow[e + 1], a1);
                a2 = fmaf(zr[e + 2], crow[e + 2], a2);
                a3 = fmaf(zr[e + 3], crow[e + 3], a3);
            }
            float part = (a0 + a1) + (a2 + a3);
            float d = (zq2 + g_csq[v]) - 2.0f * part;
            unsigned long long key = ((unsigned long long)f2ord(d) << 32) | (unsigned int)v;
            if (key < best) best = key;
        }
        #pragma unroll
        for (int o = 16; o; o >>= 1) {
            unsigned long long other = __shfl_xor_sync(0xFFFFFFFFu, best, o);
            if (other < best) best = other;
        }
        if (lane == 0) wmin[wid] = best;
        __syncthreads();
        if (t == 0) {
            unsigned long long b = wmin[0];
            #pragma unroll
            for (int k = 1; k < 8; k++) if (wmin[k] < b) b = wmin[k];
            int tok = (int)(b & 0xFFFFFFFFull);
            g_tok[pix] = tok;
            tok_out[pix] = (float)tok;
        }
        __syncthreads();
    }
}

__global__ void k_zq(const float* __restrict__ cb, float* __restrict__ zq) {
    unsigned int g = blockIdx.x * 256 + threadIdx.x;
    int hw = g & 255, e = (g >> 8) & 255, img = g >> 16;
    zq[g] = cb[(size_t)g_tok[img * 256 + hw] * 256 + e];
}

// ---------------------------------------------------------------------------
extern "C" void kernel_launch(void* const* d_in, const int* in_sizes, int n_in,
                              void* d_out, int out_size) {
    const float* x      = (const float*)d_in[0];
    const float* cb     = (const float*)d_in[1];
    const float* pre_w  = (const float*)d_in[2];
    const float* pre_b  = (const float*)d_in[3];
    const float* post_w = (const float*)d_in[4];
    const float* post_b = (const float*)d_in[5];

    float* out   = (float*)d_out;
    float* zbuf  = out;
    float* zq    = out + 8388608;
    float* recon = out + 16777216;
    float* toks  = out + 25165824;

    static bool attr_done = false;
    if (!attr_done) {
        cudaFuncSetAttribute(k_dist_mma, cudaFuncAttributeMaxDynamicSharedMemorySize, SMEM_DIST);
        attr_done = true;
    }

    k_prep<<<VOCAB, 256>>>(cb);                                        // 1
    k_gemm256<true><<<dim3(4, 4, IMGS), 256>>>(pre_w, pre_b, x, zbuf); // 2
    k_zero<<<1, 32>>>();                                               // 3
    k_dist_mma<<<NPIX / 128, 256, SMEM_DIST>>>(zbuf);                  // 4 (profiled)
    k_rescore<<<NPIX / 8, 256>>>(cb, zbuf, toks);                      // 5
    k_fallback<<<128, 256>>>(cb, zbuf, toks);                          // 6
    k_zq<<<8388608 / 256, 256>>>(cb, zq);                              // 7
    k_gemm256<false><<<dim3(4, 4, IMGS), 256>>>(post_w, post_b, zq, recon); // 8
}